// round 13
// baseline (speedup 1.0000x reference)
#include <cuda_runtime.h>
#include <cuda_bf16.h>
#include <math.h>
#include <cstdint>

#define TF 481
#define NK 48
#define NFR 8             // frames per block (M = 128)
#define NT 512
#define KT 64             // K cols per tile
#define NTILE 8           // 512 padded K
#define BROW 100
#define ARS 144           // A/B smem row stride bytes (72 bf16)

// smem map (bytes): double-buffered A and B
#define ABUF(st)  ((st)*36864)               // A_HI; A_LO at +18432
#define ALO_OFF   18432
#define BBUF(st)  (73728 + (st)*27648)       // B_HI; B_LO at +13824
#define BLO_OFF   13824
#define SM_C2B    129024                     // 512 floats
#define SMEM_BYTES 131072
// overlays (A/B dead after last MMA)
#define SM_CF  0          // 8*16*100 floats = 51200 B
#define SM_QSM 51200      // 8*48*32 floats = 49152 B -> 100352

__device__ __align__(16) __nv_bfloat16 g_bt[2 * 96 * 512];   // [split][n][k]

// ---------------- prep: band -> bf16 hi/lo, interleaved n, padded K ----------------
__global__ void pv_prep(const float* __restrict__ bandR, const float* __restrict__ bandI)
{
    int i = blockIdx.x * 256 + threadIdx.x;
    if (i >= 96 * 512) return;
    int n = i >> 9, k = i & 511;
    float val = 0.0f;
    if (k < TF) val = (n & 1) ? bandI[k*NK + (n>>1)] : bandR[k*NK + (n>>1)];
    __nv_bfloat16 h = __float2bfloat16(val);
    __nv_bfloat16 l = __float2bfloat16(val - __bfloat162float(h));
    g_bt[i] = h;
    g_bt[96*512 + i] = l;
}

__device__ __forceinline__ void mma16816(float* c, const uint32_t* a, const uint32_t* b)
{
    asm volatile(
        "mma.sync.aligned.m16n8k16.row.col.f32.bf16.bf16.f32 "
        "{%0,%1,%2,%3}, {%4,%5,%6,%7}, {%8,%9}, {%0,%1,%2,%3};"
        : "+f"(c[0]), "+f"(c[1]), "+f"(c[2]), "+f"(c[3])
        : "r"(a[0]), "r"(a[1]), "r"(a[2]), "r"(a[3]), "r"(b[0]), "r"(b[1]));
}

struct XRegs { float v[24]; };   // cr[4] ci[4] lr[4] li[4] hr[4] hx[4]

__device__ __forceinline__ void genA_load(XRegs& x_, const float* __restrict__ xr,
                                          const float* __restrict__ xi, int f)
{
    int lo = (f == 0) ? 0 : ((f == TF-1) ? TF-3 : f-1);
    int hi = lo + 2;
    #pragma unroll
    for (int ch = 0; ch < 4; ch++) {
        x_.v[ch]      = xr[ch*TF + f];   x_.v[4+ch]  = xi[ch*TF + f];
        x_.v[8+ch]    = xr[ch*TF + lo];  x_.v[12+ch] = xi[ch*TF + lo];
        x_.v[16+ch]   = xr[ch*TF + hi];  x_.v[20+ch] = xi[ch*TF + hi];
    }
}

__device__ __forceinline__ void genA_compute(const XRegs& x_, bool valid,
                                             char* ahi, char* alo, int fr, int fl)
{
    const uint32_t rowbase = (fr*16)*ARS + fl*2;
#define STC(c, val) { float _v = (val); __nv_bfloat16 _h = __float2bfloat16(_v); \
    *(__nv_bfloat16*)(ahi + rowbase + (c)*ARS) = _h; \
    *(__nv_bfloat16*)(alo + rowbase + (c)*ARS) = \
        __float2bfloat16(_v - __bfloat162float(_h)); }
    if (valid) {
        const float* cr = x_.v;      const float* ci = x_.v + 4;
        const float* lr = x_.v + 8;  const float* li = x_.v + 12;
        const float* hr = x_.v + 16; const float* hx = x_.v + 20;
        float d0 = cr[0]*cr[0]+ci[0]*ci[0];
        float d1 = cr[1]*cr[1]+ci[1]*ci[1];
        float d2 = cr[2]*cr[2]+ci[2]*ci[2];
        float d3 = cr[3]*cr[3]+ci[3]*ci[3];
        float inv = 1.0f / fmaxf(d0+d1+d2+d3, 1e-20f);
        STC(12, d0*inv) STC(13, d1*inv) STC(14, d2*inv) STC(15, d3*inv)
        const int SI[6] = {0,0,0,1,1,2};
        const int SJ[6] = {1,2,3,2,3,3};
        #pragma unroll
        for (int s = 0; s < 6; s++) {
            const int i5 = SI[s], j5 = SJ[s];
            float pcr = cr[i5]*cr[j5] + ci[i5]*ci[j5];
            float pci = ci[i5]*cr[j5] - cr[i5]*ci[j5];
            float plr = lr[i5]*lr[j5] + li[i5]*li[j5];
            float pli = li[i5]*lr[j5] - lr[i5]*li[j5];
            float phr = hr[i5]*hr[j5] + hx[i5]*hx[j5];
            float phi = hx[i5]*hr[j5] - hr[i5]*hx[j5];
            float zr = plr*phr + pli*phi;
            float zi = plr*phi - pli*phr;
            float m  = sqrtf(pcr*pcr + pci*pci) * inv;
            float z2 = zr*zr + zi*zi;
            float aR, aI;
            if (z2 > 0.0f) { float sc = m * rsqrtf(z2); aR = sc*zr; aI = sc*zi; }
            else           { aR = m; aI = 0.0f; }
            STC(2*s, aR) STC(2*s+1, aI)
        }
    } else {
        #pragma unroll
        for (int c = 0; c < 16; c++) STC(c, 0.0f)
    }
#undef STC
}

// ---------------- stage 1: 8 frames/block, pipelined HMMA bf16-split GEMM ----------------
__global__ __launch_bounds__(NT, 1) void pv_stage1(
    const float* __restrict__ binsR, const float* __restrict__ binsI,
    const float* __restrict__ c2r,  const float* __restrict__ c2i,
    float* __restrict__ out)
{
    extern __shared__ char smraw[];
    float* c2sm = (float*)(smraw + SM_C2B);

    const int tid = threadIdx.x;
    const int bt0 = blockIdx.x * NFR;
    const int b   = bt0 >> 10;
    const int t0  = bt0 & 1023;

    {   // c2pv transposed: exactly 512 items
        int v = tid & 255;
        int p = v >> 4, c = v & 15;
        float val = (tid < 256) ? c2r[tid] : c2i[v];
        c2sm[(tid < 256 ? 0 : 256) + c*16 + p] = val;
    }

    const int fr = tid >> 6;       // frame 0..7
    const int fl = tid & 63;
    const float* xr = binsR + (size_t)(bt0 + fr) * 4 * TF;
    const float* xi = binsI + (size_t)(bt0 + fr) * 4 * TF;

    const int wid  = tid >> 5, lane = tid & 31;
    const int gid  = lane >> 2, tig = lane & 3;
    const int mt   = wid & 7;      // m-tile (frame)
    const int nh   = wid >> 3;     // n half

    float acc[6][4];
    #pragma unroll
    for (int j = 0; j < 6; j++)
        #pragma unroll
        for (int v = 0; v < 4; v++) acc[j][v] = 0.0f;

    // ---- prologue: B(0) + A(0) into buffer 0 ----
    #pragma unroll
    for (int j = 0; j < 3; j++) {
        int r = j*NT + tid;
        int split = r / 768, rr = r % 768, n = rr >> 3, c4 = rr & 7;
        *(float4*)(smraw + BBUF(0) + split*BLO_OFF + n*ARS + c4*16) =
            *(const float4*)(g_bt + (size_t)split*96*512 + n*512 + 0*KT + c4*8);
    }
    {
        XRegs x0;
        genA_load(x0, xr, xi, fl);           // tile 0: f = fl, always < TF
        genA_compute(x0, true, smraw + ABUF(0), smraw + ABUF(0) + ALO_OFF, fr, fl);
    }
    __syncthreads();

    // ---- pipelined main loop ----
    for (int it = 0; it < NTILE; ++it) {
        const int st = it & 1;

        // prefetch next tile's B into regs and next tile's x into regs
        float4 breg[3];
        XRegs xn;
        bool nvalid = false;
        const int fn = (it+1) * KT + fl;
        if (it < NTILE-1) {
            #pragma unroll
            for (int j = 0; j < 3; j++) {
                int r = j*NT + tid;
                int split = r / 768, rr = r % 768, n = rr >> 3, c4 = rr & 7;
                breg[j] = *(const float4*)(g_bt + (size_t)split*96*512 + n*512 + (it+1)*KT + c4*8);
            }
            if (fn < TF) { genA_load(xn, xr, xi, fn); nvalid = true; }
        }

        // MMA on buffer st (prefetch LDGs in flight underneath)
        {
            char* ahi = smraw + ABUF(st);
            char* alo = ahi + ALO_OFF;
            char* bhi = smraw + BBUF(st);
            char* blo = bhi + BLO_OFF;
            const int arow = mt*16 + gid;
            #pragma unroll
            for (int ks = 0; ks < 4; ks++) {
                const int kb = (ks*16 + 2*tig)*2;
                uint32_t ah[4], al[4];
                ah[0] = *(const uint32_t*)(ahi + arow*ARS + kb);
                ah[1] = *(const uint32_t*)(ahi + (arow+8)*ARS + kb);
                ah[2] = *(const uint32_t*)(ahi + arow*ARS + kb + 16);
                ah[3] = *(const uint32_t*)(ahi + (arow+8)*ARS + kb + 16);
                al[0] = *(const uint32_t*)(alo + arow*ARS + kb);
                al[1] = *(const uint32_t*)(alo + (arow+8)*ARS + kb);
                al[2] = *(const uint32_t*)(alo + arow*ARS + kb + 16);
                al[3] = *(const uint32_t*)(alo + (arow+8)*ARS + kb + 16);
                #pragma unroll
                for (int j = 0; j < 6; j++) {
                    const int n = (nh*6 + j)*8 + gid;
                    uint32_t bh[2], bl[2];
                    bh[0] = *(const uint32_t*)(bhi + n*ARS + kb);
                    bh[1] = *(const uint32_t*)(bhi + n*ARS + kb + 16);
                    bl[0] = *(const uint32_t*)(blo + n*ARS + kb);
                    bl[1] = *(const uint32_t*)(blo + n*ARS + kb + 16);
                    mma16816(acc[j], ah, bh);
                    mma16816(acc[j], ah, bl);
                    mma16816(acc[j], al, bh);
                }
            }
        }

        // write next tile into buffer st^1
        if (it < NTILE-1) {
            #pragma unroll
            for (int j = 0; j < 3; j++) {
                int r = j*NT + tid;
                int split = r / 768, rr = r % 768, n = rr >> 3, c4 = rr & 7;
                *(float4*)(smraw + BBUF(st^1) + split*BLO_OFF + n*ARS + c4*16) = breg[j];
            }
            genA_compute(xn, nvalid, smraw + ABUF(st^1), smraw + ABUF(st^1) + ALO_OFF, fr, fl);
        }
        __syncthreads();
    }

    // ---- epilogue: C fragments -> smem Cf[fr][c][BROW] (single pass) ----
    {
        float* smf = (float*)(smraw + SM_CF);
        #pragma unroll
        for (int j = 0; j < 6; j++) {
            int col = (nh*6 + j)*8 + 2*tig;
            *(float2*)&smf[mt*1600 + gid*BROW + col]     = make_float2(acc[j][0], acc[j][1]);
            *(float2*)&smf[mt*1600 + (gid+8)*BROW + col] = make_float2(acc[j][2], acc[j][3]);
        }
    }
    __syncthreads();

    // ---- phase 4: reconstruct bc(complex 16) per k per frame ----
    for (int w = tid; w < NFR*192; w += NT) {
        int tl = w / 192, rr = w % 192;
        int kp = rr >> 3, slot = rr & 7;
        const float* Cfin = (const float*)(smraw + SM_CF) + tl*1600;
        float* qsm = (float*)(smraw + SM_QSM) + tl*1536;
        int m0 = (slot < 6) ? 2*slot : 12 + 2*(slot-6);
        float4 rA = *(const float4*)&Cfin[m0*BROW + 4*kp];
        float4 rB = *(const float4*)&Cfin[(m0+1)*BROW + 4*kp];
        float A0=rA.x, A1=rA.y, A4=rA.z, A5=rA.w;
        float A2=rB.x, A3=rB.y, A6=rB.z, A7=rB.w;
        float* q0 = qsm + (2*kp)*32;
        float* q1 = q0 + 32;
        if (slot < 6) {
            int i = (slot < 3) ? 0 : ((slot < 5) ? 1 : 2);
            int j = (slot < 3) ? slot+1 : ((slot < 5) ? slot-1 : 3);
            int c1 = i*4 + j, c2 = j*4 + i;
            q0[c1] = A0 - A3; q0[16+c1] = A1 + A2;
            q0[c2] = A0 + A3; q0[16+c2] = A1 - A2;
            q1[c1] = A4 - A7; q1[16+c1] = A5 + A6;
            q1[c2] = A4 + A7; q1[16+c2] = A5 - A6;
        } else {
            int d  = (slot == 6) ? 0 : 2;
            int cA = d*5, cB = (d+1)*5;
            q0[cA] = A0; q0[16+cA] = A1; q0[cB] = A2; q0[16+cB] = A3;
            q1[cA] = A4; q1[16+cA] = A5; q1[cB] = A6; q1[16+cB] = A7;
        }
    }
    __syncthreads();

    // ---- phase 5: normalize + c2pv projection (real part) ----
    for (int o = tid; o < NFR*NK*16; o += NT) {
        int tl = o / 768, r = o % 768;
        int k = r >> 4, p = r & 15;
        const float* qk = (const float*)(smraw + SM_QSM) + tl*1536 + k*32;
        float ds = fmaxf(qk[0] + qk[5] + qk[10] + qk[15], 1e-20f);
        float acc2 = 0.0f;
        #pragma unroll
        for (int c = 0; c < 16; c++) {
            acc2 += c2sm[c*16 + p] * qk[c];
            acc2 -= c2sm[256 + c*16 + p] * qk[16 + c];
        }
        out[(((size_t)b*NK + k)*1024 + (t0 + tl))*16 + p] = acc2 / ds;
    }
}

// ---------------- stage 2: chunked parallel-scan IIR ----------------
__global__ __launch_bounds__(512) void pv_iir(float* __restrict__ out,
                                              const float* __restrict__ tau)
{
    __shared__ float tails[32*16];
    __shared__ float carry[32*16];
    const int bk  = blockIdx.x;
    const int k   = bk % NK;
    const int tid = threadIdx.x;
    const int chunk = tid >> 4, p = tid & 15;

    const float a  = expf(-10.0f / tau[k]);
    const float om = 1.0f - a;
    float* base = out + ((size_t)bk * 1024 + chunk * 32) * 16 + p;

    float x[32];
    #pragma unroll
    for (int j = 0; j < 32; j++) x[j] = base[j*16];

    float l[32];
    l[0] = (chunk == 0) ? x[0] : om * x[0];
    #pragma unroll
    for (int j = 1; j < 32; j++) l[j] = a*l[j-1] + om*x[j];

    tails[chunk*16 + p] = l[31];
    __syncthreads();

    if (tid < 16) {
        float A = expf(-320.0f / tau[k]);
        float s = 0.0f;
        #pragma unroll
        for (int c = 0; c < 32; c++) {
            carry[c*16 + tid] = s;
            s = tails[c*16 + tid] + A * s;
        }
    }
    __syncthreads();

    float cin = carry[chunk*16 + p];
    float pw = a;
    #pragma unroll
    for (int j = 0; j < 32; j++) {
        base[j*16] = l[j] + pw * cin;
        pw *= a;
    }
}

extern "C" void kernel_launch(void* const* d_in, const int* in_sizes, int n_in,
                              void* d_out, int out_size)
{
    const float* binsR = (const float*)d_in[0];
    const float* binsI = (const float*)d_in[1];
    const float* bandR = (const float*)d_in[2];
    const float* bandI = (const float*)d_in[3];
    const float* c2r   = (const float*)d_in[4];
    const float* c2i   = (const float*)d_in[5];
    const float* tau   = (const float*)d_in[6];
    float* out = (float*)d_out;

    cudaFuncSetAttribute(pv_stage1, cudaFuncAttributeMaxDynamicSharedMemorySize, SMEM_BYTES);

    pv_prep<<<(96*512 + 255)/256, 256>>>(bandR, bandI);
    pv_stage1<<<512, NT, SMEM_BYTES>>>(binsR, binsI, c2r, c2i, out);
    pv_iir<<<4*NK, 512>>>(out, tau);
}

// round 14
// speedup vs baseline: 1.0781x; 1.0781x over previous
#include <cuda_runtime.h>
#include <cuda_bf16.h>
#include <math.h>
#include <cstdint>

#define TF 481
#define NK 48
#define NFR 8             // frames per block (M = 128)
#define NT 256
#define KT 64             // K cols per tile
#define NTILE 8           // 512 padded K
#define BROW 100

#define ARS 144           // A/B smem row stride bytes (72 bf16)
// smem map (bytes)
#define SM_A_HI 0         // 128*144 = 18432
#define SM_A_LO 18432
#define SM_B_HI 36864     // 96*144 = 13824
#define SM_B_LO 50688
#define SM_C2B  64512     // 512 floats
#define SMEM_BYTES 66560
// overlays (A/B dead after last MMA; per 4-frame epilogue pass)
#define SM_CF  0          // 4*16*100 floats = 25600 B
#define SM_QSM 25600      // 4*48*32 floats = 24576 B -> 50176

__device__ __align__(16) __nv_bfloat16 g_bt[2 * 96 * 512];   // [split][n][k]

// ---------------- prep: band -> bf16 hi/lo, interleaved n, padded K ----------------
__global__ void pv_prep(const float* __restrict__ bandR, const float* __restrict__ bandI)
{
    int i = blockIdx.x * 256 + threadIdx.x;
    if (i >= 96 * 512) return;
    int n = i >> 9, k = i & 511;
    float val = 0.0f;
    if (k < TF) val = (n & 1) ? bandI[k*NK + (n>>1)] : bandR[k*NK + (n>>1)];
    __nv_bfloat16 h = __float2bfloat16(val);
    __nv_bfloat16 l = __float2bfloat16(val - __bfloat162float(h));
    g_bt[i] = h;
    g_bt[96*512 + i] = l;
}

// launch-index shim so ncu's fixed skip lands on pv_stage1
__global__ void pv_nop() {}

__device__ __forceinline__ void mma16816(float* c, const uint32_t* a, const uint32_t* b)
{
    asm volatile(
        "mma.sync.aligned.m16n8k16.row.col.f32.bf16.bf16.f32 "
        "{%0,%1,%2,%3}, {%4,%5,%6,%7}, {%8,%9}, {%0,%1,%2,%3};"
        : "+f"(c[0]), "+f"(c[1]), "+f"(c[2]), "+f"(c[3])
        : "r"(a[0]), "r"(a[1]), "r"(a[2]), "r"(a[3]), "r"(b[0]), "r"(b[1]));
}

// ---------------- stage 1: 8 frames per block, HMMA bf16-split GEMM ----------------
__global__ __launch_bounds__(NT, 2) void pv_stage1(
    const float* __restrict__ binsR, const float* __restrict__ binsI,
    const float* __restrict__ c2r,  const float* __restrict__ c2i,
    float* __restrict__ out)
{
    extern __shared__ char smraw[];
    float* c2sm = (float*)(smraw + SM_C2B);

    const int tid = threadIdx.x;
    const int bt0 = blockIdx.x * NFR;
    const int b   = bt0 >> 10;
    const int t0  = bt0 & 1023;

    for (int i = tid; i < 512; i += NT) {
        int v = i & 255;
        int p = v >> 4, c = v & 15;
        float val = (i < 256) ? c2r[i] : c2i[v];
        c2sm[(i < 256 ? 0 : 256) + c*16 + p] = val;
    }

    const int fr0 = tid >> 6;      // 0..3 (item u adds 4)
    const int fl  = tid & 63;

    const int wid  = tid >> 5, lane = tid & 31;
    const int gid  = lane >> 2, tig = lane & 3;
    const int mpr  = wid & 3;      // m-tile pair: m-tiles {2mpr, 2mpr+1}
    const int nh   = wid >> 2;     // n half (6 n-tiles each)

    float acc[2][6][4];
    #pragma unroll
    for (int u = 0; u < 2; u++)
        #pragma unroll
        for (int j = 0; j < 6; j++)
            #pragma unroll
            for (int v = 0; v < 4; v++) acc[u][j][v] = 0.0f;

    char* ahi = smraw + SM_A_HI;
    char* alo = smraw + SM_A_LO;

    for (int it = 0; it < NTILE; ++it) {
        __syncthreads();    // previous tile fully consumed

        // ---- B tile copy (hi+lo) ----
        for (int i2 = tid; i2 < 1536; i2 += NT) {
            int split = i2 / 768, r = i2 % 768;
            int n = r >> 3, c4 = r & 7;
            const float4* src = (const float4*)(g_bt +
                ((size_t)split*96*512) + n*512 + it*KT + c4*8);
            *(float4*)(smraw + (split ? SM_B_LO : SM_B_HI) + n*ARS + c4*16) = *src;
        }

        // ---- A tiles: fused phase1+2 adj comps, 2 frames per thread ----
        const int f = it * KT + fl;
        #pragma unroll
        for (int u = 0; u < 2; u++) {
            const int fr = u*4 + fr0;
            const uint32_t rowbase = (fr*16)*ARS + fl*2;
#define STC(c, val) { float _v = (val); __nv_bfloat16 _h = __float2bfloat16(_v); \
            *(__nv_bfloat16*)(ahi + rowbase + (c)*ARS) = _h; \
            *(__nv_bfloat16*)(alo + rowbase + (c)*ARS) = \
                __float2bfloat16(_v - __bfloat162float(_h)); }
            if (f < TF) {
                const float* xr = binsR + (size_t)(bt0 + fr) * 4 * TF;
                const float* xi = binsI + (size_t)(bt0 + fr) * 4 * TF;
                int lo = (f == 0) ? 0 : ((f == TF-1) ? TF-3 : f-1);
                int hi = lo + 2;
                float cr[4], ci[4], lr[4], li[4], hr[4], hx[4];
                #pragma unroll
                for (int ch = 0; ch < 4; ch++) {
                    cr[ch] = xr[ch*TF + f];  ci[ch] = xi[ch*TF + f];
                    lr[ch] = xr[ch*TF + lo]; li[ch] = xi[ch*TF + lo];
                    hr[ch] = xr[ch*TF + hi]; hx[ch] = xi[ch*TF + hi];
                }
                float d0 = cr[0]*cr[0]+ci[0]*ci[0];
                float d1 = cr[1]*cr[1]+ci[1]*ci[1];
                float d2 = cr[2]*cr[2]+ci[2]*ci[2];
                float d3 = cr[3]*cr[3]+ci[3]*ci[3];
                float inv = __fdividef(1.0f, fmaxf(d0+d1+d2+d3, 1e-20f));
                STC(12, d0*inv) STC(13, d1*inv) STC(14, d2*inv) STC(15, d3*inv)
                const int SI[6] = {0,0,0,1,1,2};
                const int SJ[6] = {1,2,3,2,3,3};
                #pragma unroll
                for (int s = 0; s < 6; s++) {
                    const int i5 = SI[s], j5 = SJ[s];
                    float pcr = cr[i5]*cr[j5] + ci[i5]*ci[j5];
                    float pci = ci[i5]*cr[j5] - cr[i5]*ci[j5];
                    float plr = lr[i5]*lr[j5] + li[i5]*li[j5];
                    float pli = li[i5]*lr[j5] - lr[i5]*li[j5];
                    float phr = hr[i5]*hr[j5] + hx[i5]*hx[j5];
                    float phi = hx[i5]*hr[j5] - hr[i5]*hx[j5];
                    float zr = plr*phr + pli*phi;
                    float zi = plr*phi - pli*phr;
                    // m = sqrt(m2)*inv via MUFU only (guard m2=0 -> tiny, no NaN)
                    float m2 = fmaxf(pcr*pcr + pci*pci, 1e-35f);
                    float m  = m2 * rsqrtf(m2) * inv;
                    float z2 = zr*zr + zi*zi;
                    float aR, aI;
                    if (z2 > 0.0f) { float sc = m * rsqrtf(z2); aR = sc*zr; aI = sc*zi; }
                    else           { aR = m; aI = 0.0f; }
                    STC(2*s, aR) STC(2*s+1, aI)
                }
            } else {
                #pragma unroll
                for (int c = 0; c < 16; c++) STC(c, 0.0f)
            }
#undef STC
        }
        __syncthreads();

        // ---- MMA: 4 ksteps x (2 m-tiles x 6 n-tiles) x 3 split products ----
        #pragma unroll
        for (int ks = 0; ks < 4; ks++) {
            const int kb = (ks*16 + 2*tig)*2;
            uint32_t ah[2][4], al[2][4];
            #pragma unroll
            for (int u = 0; u < 2; u++) {
                const int arow = (2*mpr + u)*16 + gid;
                ah[u][0] = *(const uint32_t*)(ahi + arow*ARS + kb);
                ah[u][1] = *(const uint32_t*)(ahi + (arow+8)*ARS + kb);
                ah[u][2] = *(const uint32_t*)(ahi + arow*ARS + kb + 16);
                ah[u][3] = *(const uint32_t*)(ahi + (arow+8)*ARS + kb + 16);
                al[u][0] = *(const uint32_t*)(alo + arow*ARS + kb);
                al[u][1] = *(const uint32_t*)(alo + (arow+8)*ARS + kb);
                al[u][2] = *(const uint32_t*)(alo + arow*ARS + kb + 16);
                al[u][3] = *(const uint32_t*)(alo + (arow+8)*ARS + kb + 16);
            }
            #pragma unroll
            for (int j = 0; j < 6; j++) {
                const int n = (nh*6 + j)*8 + gid;
                uint32_t bh[2], bl[2];
                bh[0] = *(const uint32_t*)(smraw + SM_B_HI + n*ARS + kb);
                bh[1] = *(const uint32_t*)(smraw + SM_B_HI + n*ARS + kb + 16);
                bl[0] = *(const uint32_t*)(smraw + SM_B_LO + n*ARS + kb);
                bl[1] = *(const uint32_t*)(smraw + SM_B_LO + n*ARS + kb + 16);
                #pragma unroll
                for (int u = 0; u < 2; u++) {
                    mma16816(acc[u][j], ah[u], bh);
                    mma16816(acc[u][j], ah[u], bl);
                    mma16816(acc[u][j], al[u], bh);
                }
            }
        }
    }

    // ---- epilogue: two passes of 4 frames (CF/QSM overlay A/B) ----
    for (int pass = 0; pass < 2; pass++) {
        __syncthreads();
        if ((mpr >> 1) == pass) {
            float* smf = (float*)(smraw + SM_CF);
            #pragma unroll
            for (int u = 0; u < 2; u++) {
                const int lf = 2*(mpr & 1) + u;
                #pragma unroll
                for (int j = 0; j < 6; j++) {
                    int col = (nh*6 + j)*8 + 2*tig;
                    *(float2*)&smf[lf*1600 + gid*BROW + col] =
                        make_float2(acc[u][j][0], acc[u][j][1]);
                    *(float2*)&smf[lf*1600 + (gid+8)*BROW + col] =
                        make_float2(acc[u][j][2], acc[u][j][3]);
                }
            }
        }
        __syncthreads();

        // phase 4: reconstruct bc(complex 16) per k per frame
        for (int w = tid; w < 4*192; w += NT) {
            int tl = w / 192, rr = w % 192;
            int kp = rr >> 3, slot = rr & 7;
            const float* Cfin = (const float*)(smraw + SM_CF) + tl*1600;
            float* qsm = (float*)(smraw + SM_QSM) + tl*1536;
            int m0 = (slot < 6) ? 2*slot : 12 + 2*(slot-6);
            float4 rA = *(const float4*)&Cfin[m0*BROW + 4*kp];
            float4 rB = *(const float4*)&Cfin[(m0+1)*BROW + 4*kp];
            float A0=rA.x, A1=rA.y, A4=rA.z, A5=rA.w;
            float A2=rB.x, A3=rB.y, A6=rB.z, A7=rB.w;
            float* q0 = qsm + (2*kp)*32;
            float* q1 = q0 + 32;
            if (slot < 6) {
                int i = (slot < 3) ? 0 : ((slot < 5) ? 1 : 2);
                int j = (slot < 3) ? slot+1 : ((slot < 5) ? slot-1 : 3);
                int c1 = i*4 + j, c2 = j*4 + i;
                q0[c1] = A0 - A3; q0[16+c1] = A1 + A2;
                q0[c2] = A0 + A3; q0[16+c2] = A1 - A2;
                q1[c1] = A4 - A7; q1[16+c1] = A5 + A6;
                q1[c2] = A4 + A7; q1[16+c2] = A5 - A6;
            } else {
                int d  = (slot == 6) ? 0 : 2;
                int cA = d*5, cB = (d+1)*5;
                q0[cA] = A0; q0[16+cA] = A1; q0[cB] = A2; q0[16+cB] = A3;
                q1[cA] = A4; q1[16+cA] = A5; q1[cB] = A6; q1[16+cB] = A7;
            }
        }
        __syncthreads();

        // phase 5: normalize + c2pv projection (real part)
        for (int o = tid; o < 4*NK*16; o += NT) {
            int tl = o / 768, r = o % 768;
            int k = r >> 4, p = r & 15;
            const float* qk = (const float*)(smraw + SM_QSM) + tl*1536 + k*32;
            float ds = fmaxf(qk[0] + qk[5] + qk[10] + qk[15], 1e-20f);
            float acc2 = 0.0f;
            #pragma unroll
            for (int c = 0; c < 16; c++) {
                acc2 += c2sm[c*16 + p] * qk[c];
                acc2 -= c2sm[256 + c*16 + p] * qk[16 + c];
            }
            out[(((size_t)b*NK + k)*1024 + (t0 + pass*4 + tl))*16 + p] =
                __fdividef(acc2, ds);
        }
    }
}

// ---------------- stage 2: chunked parallel-scan IIR ----------------
__global__ __launch_bounds__(512) void pv_iir(float* __restrict__ out,
                                              const float* __restrict__ tau)
{
    __shared__ float tails[32*16];
    __shared__ float carry[32*16];
    const int bk  = blockIdx.x;
    const int k   = bk % NK;
    const int tid = threadIdx.x;
    const int chunk = tid >> 4, p = tid & 15;

    const float a  = expf(-10.0f / tau[k]);
    const float om = 1.0f - a;
    float* base = out + ((size_t)bk * 1024 + chunk * 32) * 16 + p;

    float x[32];
    #pragma unroll
    for (int j = 0; j < 32; j++) x[j] = base[j*16];

    float l[32];
    l[0] = (chunk == 0) ? x[0] : om * x[0];
    #pragma unroll
    for (int j = 1; j < 32; j++) l[j] = a*l[j-1] + om*x[j];

    tails[chunk*16 + p] = l[31];
    __syncthreads();

    if (tid < 16) {
        float A = expf(-320.0f / tau[k]);
        float s = 0.0f;
        #pragma unroll
        for (int c = 0; c < 32; c++) {
            carry[c*16 + tid] = s;
            s = tails[c*16 + tid] + A * s;
        }
    }
    __syncthreads();

    float cin = carry[chunk*16 + p];
    float pw = a;
    #pragma unroll
    for (int j = 0; j < 32; j++) {
        base[j*16] = l[j] + pw * cin;
        pw *= a;
    }
}

extern "C" void kernel_launch(void* const* d_in, const int* in_sizes, int n_in,
                              void* d_out, int out_size)
{
    const float* binsR = (const float*)d_in[0];
    const float* binsI = (const float*)d_in[1];
    const float* bandR = (const float*)d_in[2];
    const float* bandI = (const float*)d_in[3];
    const float* c2r   = (const float*)d_in[4];
    const float* c2i   = (const float*)d_in[5];
    const float* tau   = (const float*)d_in[6];
    float* out = (float*)d_out;

    cudaFuncSetAttribute(pv_stage1, cudaFuncAttributeMaxDynamicSharedMemorySize, SMEM_BYTES);

    pv_prep<<<(96*512 + 255)/256, 256>>>(bandR, bandI);
    pv_nop<<<1, 32>>>();
    pv_nop<<<1, 32>>>();
    pv_stage1<<<512, NT, SMEM_BYTES>>>(binsR, binsI, c2r, c2i, out);
    pv_iir<<<4*NK, 512>>>(out, tau);
}